// round 12
// baseline (speedup 1.0000x reference)
#include <cuda_runtime.h>
#include <math.h>

// feat: [B=4, C=256, H=50, W=50] f32;  rois: [R,5] f32;  out: [R,256,7,7] f32
#define CC 256
#define HC 128                  // half the channels: thread does c and c+128
#define HW 2500
#define HH 50
#define WW 50
#define PP 7
#define NBIN 49
#define SPATIAL_SCALE 0.0625f
#define MAX_R 512

// Packed per-(roi,bin): (hs*50+ws) in low 12 bits | 16-bit 4x4 validity mask << 16
__device__ int g_tab[MAX_R * NBIN];
// Per-roi feature base offset: b * CC * HW
__device__ int g_base[MAX_R];

__global__ void roi_setup_kernel(const float* __restrict__ rois) {
    const int r = blockIdx.x;
    const int p = threadIdx.x;           // 0..48
    const float* rp = rois + (size_t)r * 5;

    // jnp.round == round-half-to-even == rintf (RN); *0.0625 exact.
    float x1 = rintf(rp[1] * SPATIAL_SCALE);
    float y1 = rintf(rp[2] * SPATIAL_SCALE);
    float x2 = rintf(rp[3] * SPATIAL_SCALE);
    float y2 = rintf(rp[4] * SPATIAL_SCALE);
    // XLA folds x/7 into x * RN(1/7); replicate exactly.
    const float INV7 = 1.0f / 7.0f;
    float bw = __fmul_rn(fmaxf(x2 - x1 + 1.0f, 1.0f), INV7);
    float bh = __fmul_rn(fmaxf(y2 - y1 + 1.0f, 1.0f), INV7);

    float fpw = (float)(p % PP);
    float fph = (float)(p / PP);

    int ws = (int)fminf(fmaxf(floorf(__fmul_rn(bw, fpw))        + x1, 0.0f), (float)WW);
    int we = (int)fminf(fmaxf(ceilf (__fmul_rn(bw, fpw + 1.0f)) + x1, 0.0f), (float)WW);
    int hs = (int)fminf(fmaxf(floorf(__fmul_rn(bh, fph))        + y1, 0.0f), (float)HH);
    int he = (int)fminf(fmaxf(ceilf (__fmul_rn(bh, fph + 1.0f)) + y1, 0.0f), (float)HH);

    int nw = we - ws;                    // 0..4 (window provably <= 4x4)
    int nh = he - hs;                    // 0..4
    unsigned rowpat = (nw > 0) ? ((1u << nw) - 1u) : 0u;
    unsigned rows   = (nh > 0) ? (0x1111u & ((1u << (4 * nh)) - 1u)) : 0u;
    unsigned mask   = rowpat * rows;     // bit (i*4+j) set iff i<nh && j<nw

    g_tab[r * NBIN + p] = (hs * WW + ws) | ((int)mask << 16);
    if (p == 0) g_base[r] = (int)rp[0] * (CC * HW);
}

__global__ void __launch_bounds__(256)
roipool_kernel(const float* __restrict__ feat,
               float* __restrict__ out, int total) {
    int idx = blockIdx.x * blockDim.x + threadIdx.x;
    if (idx >= total) return;

    int p  = idx % NBIN;
    int rc = idx / NBIN;            // r*128 + c  (c in 0..127)
    int r  = rc >> 7;
    int c  = rc & 127;

    int tab = __ldg(&g_tab[r * NBIN + p]);
    unsigned mask = ((unsigned)tab) >> 16;
    int off = tab & 0xFFF;

    const float* baseA = feat + __ldg(&g_base[r]) + c * HW + off;
    const float* baseB = baseA + HC * HW;     // channel c+128

    // Shared predicates: one mask test drives the gather for BOTH channels.
    float a0 = -INFINITY, a1 = -INFINITY, a2 = -INFINITY, a3 = -INFINITY;
    float b0 = -INFINITY, b1 = -INFINITY, b2 = -INFINITY, b3 = -INFINITY;
    #pragma unroll
    for (int i = 0; i < 4; ++i) {
        if (mask & (1u << (i * 4 + 0))) {
            a0 = fmaxf(a0, __ldg(baseA + i * WW + 0));
            b0 = fmaxf(b0, __ldg(baseB + i * WW + 0));
        }
        if (mask & (1u << (i * 4 + 1))) {
            a1 = fmaxf(a1, __ldg(baseA + i * WW + 1));
            b1 = fmaxf(b1, __ldg(baseB + i * WW + 1));
        }
        if (mask & (1u << (i * 4 + 2))) {
            a2 = fmaxf(a2, __ldg(baseA + i * WW + 2));
            b2 = fmaxf(b2, __ldg(baseB + i * WW + 2));
        }
        if (mask & (1u << (i * 4 + 3))) {
            a3 = fmaxf(a3, __ldg(baseA + i * WW + 3));
            b3 = fmaxf(b3, __ldg(baseB + i * WW + 3));
        }
    }
    float ma = fmaxf(fmaxf(a0, a1), fmaxf(a2, a3));
    float mb = fmaxf(fmaxf(b0, b1), fmaxf(b2, b3));

    // Output indices: ((r*256 + c)*49 + p) and ((r*256 + c+128)*49 + p)
    size_t oA = ((size_t)(r * CC + c)) * NBIN + p;
    out[oA]                      = (ma == -INFINITY) ? 0.0f : ma;
    out[oA + (size_t)HC * NBIN]  = (mb == -INFINITY) ? 0.0f : mb;
}

extern "C" void kernel_launch(void* const* d_in, const int* in_sizes, int n_in,
                              void* d_out, int out_size) {
    const float* feat = (const float*)d_in[0];
    const float* rois = (const float*)d_in[1];
    float* out = (float*)d_out;

    int R = in_sizes[1] / 5;             // 128
    int total = R * HC * NBIN;           // 802,816 threads (2 outputs each)

    roi_setup_kernel<<<R, NBIN>>>(rois);

    int threads = 256;
    int blocks = (total + threads - 1) / threads;
    roipool_kernel<<<blocks, threads>>>(feat, out, total);
}